// round 13
// baseline (speedup 1.0000x reference)
#include <cuda_runtime.h>
#include <cstdint>

// SpikeFP32Tanh: [N,32] MSB-first 0/1 float pulses of FP32 values ->
// pack to FP32 word, promote to FP64, t = (e^{2v}-1)/(e^{2v}+1) in FP64,
// round to FP32, unpack to [N,32] pulses.
//
// R13 == R7..R12 resubmission (R4..R12 all broker timeouts; never ran).
// vs R3 (230us, DRAM 56%, limiter = ~128B in flight per warp; ptxas
// interleaves load/consumer):
//  - Loads widened to 8x LDG.128: >=512B/warp in flight at ANY schedule.
//  - Pack loop fissioned at the nibble: Loop A does LDG.128 -> 4-bit nib
//    (8 regs buffered, cheap -> fission survives ptxas, loads front-batch
//    up to 4KB/warp). Loop B does REDUX.OR + SHFL redistribution only.
//  - Stores remain 8x STG.128.

__global__ void __launch_bounds__(256)
spike_tanh_kernel(const uint32_t* __restrict__ x, uint32_t* __restrict__ out,
                  int n_elems)
{
    const unsigned FULL = 0xFFFFFFFFu;
    const unsigned ONEF = 0x3F800000u;            // 1.0f bit pattern
    int warp_id = (blockIdx.x * blockDim.x + threadIdx.x) >> 5;
    int lane    = threadIdx.x & 31;
    int base    = warp_id * 32;                   // first row of this warp
    if (base >= n_elems) return;                  // N % 32 == 0: warp-uniform

    const uint4* __restrict__ xin4  = (const uint4*)(x   + (size_t)base * 32);
    uint4*       __restrict__ xout4 = (uint4*)      (out + (size_t)base * 32);

    int g = lane >> 3;                            // subgroup = row offset 0..3
    int q = lane & 7;                             // 16B chunk within row
    unsigned grp_mask = 0xFFu << (g * 8);         // 8-lane reduce partition
    int s_nib = 28 - 4 * q;                       // nibble's IEEE bit offset

    // ---- Loop A: 8 independent LDG.128 + nibble extract (memory phase)
    unsigned nib[8];
    #pragma unroll
    for (int i = 0; i < 8; ++i) {
        uint4 v = xin4[i * 32 + lane];            // row 4i+g, pulses 4q..4q+3
        // pulse bit = bit29 of (0 | 0x3F800000); MSB-first -> IEEE bit 31-k
        nib[i] = (((v.x >> 29) & 1u) << 3) | (((v.y >> 29) & 1u) << 2) |
                 (((v.z >> 29) & 1u) << 1) |  ((v.w >> 29) & 1u);
    }

    // ---- Loop B: assemble row words; lane l ends with row (base+l)'s word
    unsigned u = 0u;
    #pragma unroll
    for (int i = 0; i < 8; ++i) {
        unsigned wv = __reduce_or_sync(grp_mask, nib[i] << s_nib); // row 4i+g
        // lane l wants row l = 4(l>>2)+(l&3): group (l&3)'s word at iter l>>2
        unsigned got = __shfl_sync(FULL, wv, (lane & 3) * 8);
        if ((lane >> 2) == i) u = got;
    }

    // ---- FP64 circuit: exact reference formula
    double v64 = (double)__uint_as_float(u);
    double e2x = exp(2.0 * v64);
    double t64 = (e2x - 1.0) / (e2x + 1.0);
    unsigned ru = __float_as_uint((float)t64);

    // ---- unpack: 8 SHFL + 8 STG.128; iter i writes rows 4i..4i+3
    int s0 = 31 - 4 * q;
    #pragma unroll
    for (int i = 0; i < 8; ++i) {
        unsigned rj = __shfl_sync(FULL, ru, 4 * i + g);  // row 4i+g's word
        uint4 v;
        v.x = ((rj >> (s0    )) & 1u) * ONEF;
        v.y = ((rj >> (s0 - 1)) & 1u) * ONEF;
        v.z = ((rj >> (s0 - 2)) & 1u) * ONEF;
        v.w = ((rj >> (s0 - 3)) & 1u) * ONEF;
        xout4[i * 32 + lane] = v;
    }
}

extern "C" void kernel_launch(void* const* d_in, const int* in_sizes, int n_in,
                              void* d_out, int out_size)
{
    const uint32_t* x = (const uint32_t*)d_in[0];
    uint32_t* out     = (uint32_t*)d_out;
    int n_elems       = in_sizes[0] / 32;         // 4,194,304 rows

    const int threads = 256;                      // 8 warps -> 256 rows/block
    int warps  = (n_elems + 31) / 32;
    int blocks = (warps + 7) / 8;
    spike_tanh_kernel<<<blocks, threads>>>(x, out, n_elems);
}

// round 16
// speedup vs baseline: 1.1068x; 1.1068x over previous
#include <cuda_runtime.h>
#include <cstdint>

// SpikeFP32Tanh: [N,32] MSB-first 0/1 float pulses -> pack FP32 word ->
// FP64 (e^{2v}-1)/(e^{2v}+1) -> FP32 -> unpack pulses.
//
// R16 == R14/R15 resubmission (both broker timeouts; never ran).
// cp.async redesign. R3 (230us, DRAM 56%) and R13 (252us, DRAM 51%,
// regs=34) both proved ptxas serializes register-destination loads behind
// their consumers (MLP~1) regardless of source structure. cp.async has no
// destination register -> cannot be serialized: 8x16B copies issue
// back-to-back into a 32KB smem tile (SW128-swizzled), one wait+barrier,
// then pack is pure thread-local ALU from smem. Unpack keeps the
// rel_err-0-validated SHFL + 8x STG.128 path from R13. 7 resident
// blocks/SM overlap each other's load/pack phases.

__global__ void __launch_bounds__(256)
spike_tanh_kernel(const uint32_t* __restrict__ x, uint32_t* __restrict__ out)
{
    const unsigned FULL = 0xFFFFFFFFu;
    const unsigned ONEF = 0x3F800000u;                 // 1.0f bit pattern
    __shared__ __align__(16) char tile[256 * 128];     // 256 rows x 128 B

    int t    = threadIdx.x;
    int lane = t & 31;
    int w    = t >> 5;                                 // warp in block

    uint32_t sbase = (uint32_t)__cvta_generic_to_shared(tile);

    // ---- phase 1: 8x cp.async.cg 16B per thread, chunk-major, swizzled dst
    // block tile = 2048 16B chunks; chunk gidx -> row gidx>>3, chunk gidx&7
    const char* gsrc = (const char*)x + (size_t)blockIdx.x * 32768;
    #pragma unroll
    for (int i = 0; i < 8; ++i) {
        int gidx = i * 256 + t;
        int r = gidx >> 3, c = gidx & 7;
        uint32_t dst = sbase + r * 128 + ((c ^ (r & 7)) << 4); // SW128 swizzle
        asm volatile("cp.async.cg.shared.global [%0], [%1], 16;\n"
                     :: "r"(dst), "l"(gsrc + (size_t)gidx * 16));
    }
    asm volatile("cp.async.commit_group;\n");
    asm volatile("cp.async.wait_group 0;\n" ::: "memory");
    __syncthreads();                                   // all threads' copies visible

    // ---- phase 2: pack row t from smem (row-major, conflict-free reads)
    uint32_t rowbase = sbase + t * 128;
    int rsw = t & 7;
    unsigned u = 0u;
    #pragma unroll
    for (int c = 0; c < 8; ++c) {
        uint32_t a = rowbase + ((c ^ rsw) << 4);
        unsigned vx, vy, vz, vw;
        asm volatile("ld.shared.v4.u32 {%0,%1,%2,%3}, [%4];\n"
                     : "=r"(vx), "=r"(vy), "=r"(vz), "=r"(vw) : "r"(a));
        // pulse bit = bit29 of (0 | 0x3F800000); pulse 4c+k -> IEEE bit 31-(4c+k)
        int s = 28 - 4 * c;
        u |= (((vx >> 29) & 1u) << (s + 3)) | (((vy >> 29) & 1u) << (s + 2)) |
             (((vz >> 29) & 1u) << (s + 1)) | (((vw >> 29) & 1u) <<  s     );
    }

    // ---- phase 3: FP64 circuit, literal reference formula
    double v64 = (double)__uint_as_float(u);
    double e2x = exp(2.0 * v64);
    double t64 = (e2x - 1.0) / (e2x + 1.0);
    unsigned ru = __float_as_uint((float)t64);

    // ---- phase 4: unpack via SHFL + 8x STG.128 (validated in R13)
    // warp w owns rows blockIdx.x*256 + w*32 + [0..31]; lane l holds row l's word
    uint4* xout4 = (uint4*)out + ((size_t)blockIdx.x * 256 + w * 32) * 8;
    int g  = lane >> 3;                                // row offset within iter
    int q  = lane & 7;                                 // 16B chunk within row
    int s0 = 31 - 4 * q;
    #pragma unroll
    for (int i = 0; i < 8; ++i) {
        unsigned rj = __shfl_sync(FULL, ru, 4 * i + g); // row 4i+g's word
        uint4 v;
        v.x = ((rj >> (s0    )) & 1u) * ONEF;
        v.y = ((rj >> (s0 - 1)) & 1u) * ONEF;
        v.z = ((rj >> (s0 - 2)) & 1u) * ONEF;
        v.w = ((rj >> (s0 - 3)) & 1u) * ONEF;
        xout4[i * 32 + lane] = v;                       // row 4i+g, chunk q
    }
}

extern "C" void kernel_launch(void* const* d_in, const int* in_sizes, int n_in,
                              void* d_out, int out_size)
{
    const uint32_t* x = (const uint32_t*)d_in[0];
    uint32_t* out     = (uint32_t*)d_out;
    int n_elems       = in_sizes[0] / 32;              // 4,194,304 rows
    int blocks        = n_elems / 256;                 // 16384 (exact)
    spike_tanh_kernel<<<blocks, 256>>>(x, out);
}